// round 9
// baseline (speedup 1.0000x reference)
#include <cuda_runtime.h>
#include <cuda_bf16.h>
#include <cuda_fp16.h>
#include <cstdint>

#define N_NODES 100000
#define N_FEAT  512
#define HIDDEN  128
#define N_CLASS 16
#define N_EDGES 3200000
#define ALPHA   0.25f

#define NCHUNK 98   // ceil(100000/1024)

// ---------------- device scratch ----------------
__device__ float  g_local[N_NODES * N_CLASS];      // fp32 local logits (self term)
__device__ __half g_localh[N_NODES * N_CLASS];     // fp16 gather table, iter 1
__device__ __half g_tmph[N_NODES * N_CLASS];       // fp16 gather table, iter 2
__device__ int    g_cnt[N_NODES];
__device__ int    g_rowptr[N_NODES + 1];
__device__ int    g_fill[N_NODES];
__device__ float  g_scale[N_NODES];
__device__ int    g_csr[N_EDGES];
__device__ int    g_chunksum[NCHUNK];
__device__ uint32_t g_W1t[N_FEAT * HIDDEN];        // W1 pre-converted to tf32 (rna)

// ---------------- helpers ----------------
__device__ __forceinline__ uint32_t f2tf(float f) {
    uint32_t u;
    asm("cvt.rna.tf32.f32 %0, %1;" : "=r"(u) : "f"(f));
    return u;
}

__device__ __forceinline__ uint32_t packh(float a, float b) {
    __half2 t = __floats2half2_rn(a, b);
    return *(uint32_t*)&t;
}

__device__ __forceinline__ void mma_tf32(float* d,
                                         uint32_t a0, uint32_t a1, uint32_t a2, uint32_t a3,
                                         uint32_t b0, uint32_t b1) {
    asm volatile(
        "mma.sync.aligned.m16n8k8.row.col.f32.tf32.tf32.f32 "
        "{%0,%1,%2,%3},{%4,%5,%6,%7},{%8,%9},{%0,%1,%2,%3};\n"
        : "+f"(d[0]), "+f"(d[1]), "+f"(d[2]), "+f"(d[3])
        : "r"(a0), "r"(a1), "r"(a2), "r"(a3), "r"(b0), "r"(b1));
}

__device__ __forceinline__ void cp16(uint32_t dst, const void* src) {
    asm volatile("cp.async.cg.shared.global [%0], [%1], 16;\n"
                 :: "r"(dst), "l"(src) : "memory");
}
#define CP_COMMIT asm volatile("cp.async.commit_group;\n" ::: "memory")
#define CP_WAIT(N) asm volatile("cp.async.wait_group %0;\n" :: "n"(N) : "memory")

// ---------------- W1 pre-conversion (rna) ----------------
__global__ void k_cvt_w1(const float* __restrict__ W1) {
    int i = blockIdx.x * blockDim.x + threadIdx.x;
    if (i < N_FEAT * HIDDEN) g_W1t[i] = f2tf(W1[i]);
}

// ---------------- CSR build ----------------
__global__ void k_zero_cnt() {
    int i = blockIdx.x * blockDim.x + threadIdx.x;
    if (i < N_NODES) g_cnt[i] = 0;
    if (i == 0) g_rowptr[N_NODES] = N_EDGES;   // total is a compile-time constant
}

__global__ void k_hist(const int* __restrict__ esrc) {
    int t = blockIdx.x * blockDim.x + threadIdx.x;
    if (t < N_EDGES / 4) {
        int4 s = ((const int4*)esrc)[t];
        atomicAdd(&g_cnt[s.x], 1);
        atomicAdd(&g_cnt[s.y], 1);
        atomicAdd(&g_cnt[s.z], 1);
        atomicAdd(&g_cnt[s.w], 1);
    }
}

// scan phase 1: per-1024-chunk sums
__global__ void k_scan1() {
    __shared__ int ws[32];
    int tid = threadIdx.x, lane = tid & 31, wid = tid >> 5;
    int i = blockIdx.x * 1024 + tid;
    int v = (i < N_NODES) ? g_cnt[i] : 0;
    #pragma unroll
    for (int d = 16; d >= 1; d >>= 1) v += __shfl_xor_sync(0xffffffffu, v, d);
    if (lane == 0) ws[wid] = v;
    __syncthreads();
    if (wid == 0) {
        int s = ws[lane];
        #pragma unroll
        for (int d = 16; d >= 1; d >>= 1) s += __shfl_xor_sync(0xffffffffu, s, d);
        if (lane == 0) g_chunksum[blockIdx.x] = s;
    }
}

// scan phase 3: chunk-prefix (folded in) + in-chunk exclusive scan; writes rowptr/fill/scale
__global__ void k_scan3() {
    __shared__ int ws[32];
    __shared__ int s_pre[4];
    int tid = threadIdx.x, lane = tid & 31, wid = tid >> 5;

    // prefix of chunk sums over chunks < blockIdx.x (NCHUNK=98 < 128)
    if (tid < 128) {
        int vp = (tid < blockIdx.x) ? g_chunksum[tid] : 0;
        #pragma unroll
        for (int d = 16; d >= 1; d >>= 1) vp += __shfl_xor_sync(0xffffffffu, vp, d);
        if (lane == 0) s_pre[wid] = vp;
    }

    int i = blockIdx.x * 1024 + tid;
    int v = (i < N_NODES) ? g_cnt[i] : 0;
    int x = v;
    #pragma unroll
    for (int d = 1; d < 32; d <<= 1) {
        int y = __shfl_up_sync(0xffffffffu, x, d);
        if (lane >= d) x += y;
    }
    if (lane == 31) ws[wid] = x;
    __syncthreads();
    if (wid == 0) {
        int w = ws[lane];
        int xs = w;
        #pragma unroll
        for (int d = 1; d < 32; d <<= 1) {
            int y = __shfl_up_sync(0xffffffffu, xs, d);
            if (lane >= d) xs += y;
        }
        ws[lane] = xs;
    }
    __syncthreads();
    int coff = s_pre[0] + s_pre[1] + s_pre[2] + s_pre[3];
    int warp_prefix = (wid > 0) ? ws[wid - 1] : 0;
    int excl = x - v + warp_prefix + coff;
    if (i < N_NODES) {
        g_rowptr[i] = excl;
        g_fill[i]   = excl;
        g_scale[i]  = (1.0f - ALPHA) / fmaxf((float)v, 1e-12f);
    }
}

__global__ void k_scatter(const int* __restrict__ esrc, const int* __restrict__ edst) {
    int t = blockIdx.x * blockDim.x + threadIdx.x;
    if (t < N_EDGES / 4) {
        int4 s = ((const int4*)esrc)[t];
        int4 d = ((const int4*)edst)[t];
        int p;
        p = atomicAdd(&g_fill[s.x], 1); g_csr[p] = d.x;
        p = atomicAdd(&g_fill[s.y], 1); g_csr[p] = d.y;
        p = atomicAdd(&g_fill[s.z], 1); g_csr[p] = d.z;
        p = atomicAdd(&g_fill[s.w], 1); g_csr[p] = d.w;
    }
}

// ---------------- fused GEMM: local = relu(x@W1) @ W2 ----------------
#define GBM 128
#define GBK 32
#define ASTR 36
#define BSTR 136
#define A_BYTES (GBM * ASTR * 4)            // 18432
#define B_BYTES (GBK * BSTR * 4)            // 17408
#define STAGE_BYTES (A_BYTES + B_BYTES)     // 35840
#define W2_OFF (2 * STAGE_BYTES)            // 71680
#define OUTS_OFF (W2_OFF + HIDDEN * N_CLASS * 4)  // 79872
#define OUTSTR 17
#define GEMM_SMEM (OUTS_OFF + GBM * OUTSTR * 4)   // 88576
#define HIDSTR 129

__global__ __launch_bounds__(256, 2) void k_gemm(const float* __restrict__ x,
                                                 const float* __restrict__ W2) {
    extern __shared__ __align__(16) char sm[];
    float* W2s  = (float*)(sm + W2_OFF);
    float* outS = (float*)(sm + OUTS_OFF);
    float* hid  = (float*)sm;
    uint32_t smem_u32 = (uint32_t)__cvta_generic_to_shared(sm);

    int tid  = threadIdx.x;
    int lane = tid & 31;
    int warp = tid >> 5;
    int blockRow = blockIdx.x * GBM;

    int warpM = warp >> 1;   // 0..3
    int warpN = warp & 1;    // 0..1
    int grp = lane >> 2;     // 0..7
    int tig = lane & 3;      // 0..3

    for (int i = tid; i < HIDDEN * N_CLASS; i += 256) W2s[i] = W2[i];

    float acc[2][8][4];
    #pragma unroll
    for (int mt = 0; mt < 2; mt++)
        #pragma unroll
        for (int nt = 0; nt < 8; nt++)
            #pragma unroll
            for (int r = 0; r < 4; r++) acc[mt][nt][r] = 0.0f;

    auto load_tiles = [&](int kiter, int st) {
        int k0 = kiter * GBK;
        uint32_t abase = smem_u32 + st * STAGE_BYTES;
        uint32_t bbase = abase + A_BYTES;
        #pragma unroll
        for (int it = 0; it < 4; it++) {
            int idx = tid + it * 256;
            int r = idx >> 3, c4 = idx & 7;
            int gr = blockRow + r;
            if (gr >= N_NODES) gr = N_NODES - 1;
            cp16(abase + (r * ASTR + c4 * 4) * 4,
                 &x[(size_t)gr * N_FEAT + k0 + c4 * 4]);
        }
        #pragma unroll
        for (int it = 0; it < 4; it++) {
            int idx = tid + it * 256;
            int r = idx >> 5, c4 = idx & 31;
            cp16(bbase + (r * BSTR + c4 * 4) * 4,
                 &g_W1t[(k0 + r) * HIDDEN + c4 * 4]);
        }
    };

    auto compute = [&](int st) {
        const uint32_t* As = (const uint32_t*)(sm + st * STAGE_BYTES);
        const uint32_t* Bs = (const uint32_t*)(sm + st * STAGE_BYTES + A_BYTES);
        #pragma unroll
        for (int ks = 0; ks < 4; ks++) {
            int kk = ks * 8;
            uint32_t a[2][4];
            #pragma unroll
            for (int mt = 0; mt < 2; mt++) {
                int r0 = warpM * 32 + mt * 16 + grp;
                a[mt][0] = f2tf(__uint_as_float(As[r0 * ASTR + kk + tig]));
                a[mt][1] = f2tf(__uint_as_float(As[(r0 + 8) * ASTR + kk + tig]));
                a[mt][2] = f2tf(__uint_as_float(As[r0 * ASTR + kk + tig + 4]));
                a[mt][3] = f2tf(__uint_as_float(As[(r0 + 8) * ASTR + kk + tig + 4]));
            }
            #pragma unroll
            for (int nt = 0; nt < 8; nt++) {
                int col = warpN * 64 + nt * 8 + grp;
                uint32_t b0 = Bs[(kk + tig) * BSTR + col];
                uint32_t b1 = Bs[(kk + tig + 4) * BSTR + col];
                mma_tf32(acc[0][nt], a[0][0], a[0][1], a[0][2], a[0][3], b0, b1);
                mma_tf32(acc[1][nt], a[1][0], a[1][1], a[1][2], a[1][3], b0, b1);
            }
        }
    };

    load_tiles(0, 0);
    CP_COMMIT;
    #pragma unroll 1
    for (int i = 0; i < N_FEAT / GBK; i++) {
        int st = i & 1;
        if (i + 1 < N_FEAT / GBK) {
            load_tiles(i + 1, st ^ 1);
            CP_COMMIT;
            CP_WAIT(1);
        } else {
            CP_WAIT(0);
        }
        __syncthreads();
        compute(st);
        __syncthreads();
    }

    // relu -> hid
    #pragma unroll
    for (int mt = 0; mt < 2; mt++) {
        int r0 = warpM * 32 + mt * 16 + grp;
        #pragma unroll
        for (int nt = 0; nt < 8; nt++) {
            int c = warpN * 64 + nt * 8 + tig * 2;
            hid[r0 * HIDSTR + c]           = fmaxf(acc[mt][nt][0], 0.f);
            hid[r0 * HIDSTR + c + 1]       = fmaxf(acc[mt][nt][1], 0.f);
            hid[(r0 + 8) * HIDSTR + c]     = fmaxf(acc[mt][nt][2], 0.f);
            hid[(r0 + 8) * HIDSTR + c + 1] = fmaxf(acc[mt][nt][3], 0.f);
        }
    }
    __syncthreads();

    // second gemm: out[128][16] = hid[128][128] @ W2[128][16], 2-way h split
    int r = tid & 127;
    int q = tid >> 7;  // 0..1
    float o[N_CLASS];
    #pragma unroll
    for (int c = 0; c < N_CLASS; c++) o[c] = 0.f;
    int h0 = q * 64;
    #pragma unroll 4
    for (int h = h0; h < h0 + 64; h++) {
        float v = hid[r * HIDSTR + h];
        #pragma unroll
        for (int c = 0; c < N_CLASS; c++) o[c] += v * W2s[h * N_CLASS + c];
    }
    if (q == 0) {
        #pragma unroll
        for (int c = 0; c < N_CLASS; c++) outS[r * OUTSTR + c] = o[c];
    }
    __syncthreads();
    if (q == 1) {
        int gr = blockRow + r;
        if (gr < N_NODES) {
            float vv[N_CLASS];
            #pragma unroll
            for (int c = 0; c < N_CLASS; c++) vv[c] = outS[r * OUTSTR + c] + o[c];
            #pragma unroll
            for (int j = 0; j < 4; j++) {
                float4 v4 = make_float4(vv[j*4+0], vv[j*4+1], vv[j*4+2], vv[j*4+3]);
                *(float4*)&g_local[gr * N_CLASS + j * 4] = v4;
            }
            // fp16 gather table (32B per node = one L2 sector)
            uint4 h0v, h1v;
            h0v.x = packh(vv[0],  vv[1]);  h0v.y = packh(vv[2],  vv[3]);
            h0v.z = packh(vv[4],  vv[5]);  h0v.w = packh(vv[6],  vv[7]);
            h1v.x = packh(vv[8],  vv[9]);  h1v.y = packh(vv[10], vv[11]);
            h1v.z = packh(vv[12], vv[13]); h1v.w = packh(vv[14], vv[15]);
            *(uint4*)&g_localh[gr * N_CLASS]     = h0v;
            *(uint4*)&g_localh[gr * N_CLASS + 8] = h1v;
        }
    }
}

// ---------------- SpMM: 16 lanes = 16 classes per node, fp16 gather tables ----------------
template<int PHASE>
__global__ void k_spmm_t(float* __restrict__ outfinal) {
    const __half* tbl = (PHASE == 0) ? g_localh : g_tmph;
    int t = blockIdx.x * blockDim.x + threadIdx.x;
    int node = t >> 4;
    if (node >= N_NODES) return;
    int l16 = threadIdx.x & 15;
    unsigned mask = 0xFFFFu << (threadIdx.x & 16);

    int s = g_rowptr[node], e = g_rowptr[node + 1];
    float a = 0.f;
    int i = s;
    for (; i + 16 <= e; i += 16) {
        int idx = __ldg(&g_csr[i + l16]);
        #pragma unroll
        for (int q = 0; q < 16; q++) {
            int j = __shfl_sync(mask, idx, q, 16);
            a += __half2float(__ldg(&tbl[j * N_CLASS + l16]));
        }
    }
    int rem = e - i;
    if (rem) {
        int idx = (l16 < rem) ? __ldg(&g_csr[i + l16]) : 0;
        for (int q = 0; q < rem; q++) {
            int j = __shfl_sync(mask, idx, q, 16);
            a += __half2float(__ldg(&tbl[j * N_CLASS + l16]));
        }
    }
    float v = g_scale[node] * a + ALPHA * g_local[node * N_CLASS + l16];

    if (PHASE == 0) {
        g_tmph[node * N_CLASS + l16] = __float2half_rn(v);
    } else {
        float m = v;
        #pragma unroll
        for (int k = 8; k >= 1; k >>= 1) m = fmaxf(m, __shfl_xor_sync(mask, m, k, 16));
        float ex = __expf(v - m);
        float ss = ex;
        #pragma unroll
        for (int k = 8; k >= 1; k >>= 1) ss += __shfl_xor_sync(mask, ss, k, 16);
        outfinal[node * N_CLASS + l16] = v - m - __logf(ss);
    }
}

// ---------------- launch: fork CSR chain onto side stream, join before SpMM ----------------
extern "C" void kernel_launch(void* const* d_in, const int* in_sizes, int n_in,
                              void* d_out, int out_size) {
    const float* x    = (const float*)d_in[0];
    const float* W1   = (const float*)d_in[1];
    const float* W2   = (const float*)d_in[2];
    const int*   esrc = (const int*)d_in[3];
    const int*   edst = (const int*)d_in[4];
    float* out = (float*)d_out;

    static cudaStream_t s2 = nullptr;
    static cudaEvent_t evFork = nullptr, evJoin = nullptr;
    if (s2 == nullptr) {
        cudaStreamCreateWithFlags(&s2, cudaStreamNonBlocking);
        cudaEventCreateWithFlags(&evFork, cudaEventDisableTiming);
        cudaEventCreateWithFlags(&evJoin, cudaEventDisableTiming);
        cudaFuncSetAttribute(k_gemm, cudaFuncAttributeMaxDynamicSharedMemorySize, GEMM_SMEM);
    }

    // fork
    cudaEventRecord(evFork, 0);
    cudaStreamWaitEvent(s2, evFork, 0);

    // chain A: CSR build (side stream) — L2/atomic-bound, complements GEMM
    k_zero_cnt<<<(N_NODES + 255) / 256, 256, 0, s2>>>();
    k_hist<<<(N_EDGES / 4 + 255) / 256, 256, 0, s2>>>(esrc);
    k_scan1<<<NCHUNK, 1024, 0, s2>>>();
    k_scan3<<<NCHUNK, 1024, 0, s2>>>();
    k_scatter<<<(N_EDGES / 4 + 255) / 256, 256, 0, s2>>>(esrc, edst);
    cudaEventRecord(evJoin, s2);

    // chain B: features (main stream) — tensor/smem-bound
    k_cvt_w1<<<(N_FEAT * HIDDEN + 255) / 256, 256>>>(W1);
    k_gemm<<<(N_NODES + GBM - 1) / GBM, 256, GEMM_SMEM>>>(x, W2);

    // join, then propagation
    cudaStreamWaitEvent(0, evJoin, 0);
    k_spmm_t<0><<<(N_NODES * N_CLASS + 255) / 256, 256>>>(nullptr);
    k_spmm_t<1><<<(N_NODES * N_CLASS + 255) / 256, 256>>>(out);
}

// round 10
// speedup vs baseline: 1.0965x; 1.0965x over previous
#include <cuda_runtime.h>
#include <cuda_bf16.h>
#include <cuda_fp16.h>
#include <cstdint>

#define N_NODES 100000
#define N_FEAT  512
#define HIDDEN  128
#define N_CLASS 16
#define N_EDGES 3200000
#define ALPHA   0.25f

#define NCHUNK 98   // ceil(100000/1024)

// ---------------- device scratch ----------------
__device__ float  g_local[N_NODES * N_CLASS];      // fp32 local logits (self term)
__device__ __half g_localh[N_NODES * N_CLASS];     // fp16 gather table, iter 1
__device__ __half g_tmph[N_NODES * N_CLASS];       // fp16 gather table, iter 2
__device__ int    g_cnt[N_NODES];
__device__ int    g_rowptr[N_NODES + 1];
__device__ int    g_fill[N_NODES];
__device__ float  g_scale[N_NODES];
__device__ int    g_csr[N_EDGES];
__device__ int    g_chunksum[NCHUNK];
__device__ uint32_t g_W1h[(N_FEAT / 2) * HIDDEN];  // W1 packed as half2 over k-pairs

// ---------------- helpers ----------------
__device__ __forceinline__ uint32_t packh(float a, float b) {
    __half2 t = __floats2half2_rn(a, b);
    return *(uint32_t*)&t;
}

__device__ __forceinline__ void mma_f16(float* d, const uint32_t* a,
                                        uint32_t b0, uint32_t b1) {
    asm volatile(
        "mma.sync.aligned.m16n8k16.row.col.f32.f16.f16.f32 "
        "{%0,%1,%2,%3},{%4,%5,%6,%7},{%8,%9},{%0,%1,%2,%3};\n"
        : "+f"(d[0]), "+f"(d[1]), "+f"(d[2]), "+f"(d[3])
        : "r"(a[0]), "r"(a[1]), "r"(a[2]), "r"(a[3]), "r"(b0), "r"(b1));
}

__device__ __forceinline__ void cp16(uint32_t dst, const void* src) {
    asm volatile("cp.async.cg.shared.global [%0], [%1], 16;\n"
                 :: "r"(dst), "l"(src) : "memory");
}
#define CP_COMMIT asm volatile("cp.async.commit_group;\n" ::: "memory")
#define CP_WAIT(N) asm volatile("cp.async.wait_group %0;\n" :: "n"(N) : "memory")

// ---------------- W1 pre-conversion: pack (k, k+1) pairs into half2 ----------------
__global__ void k_cvt_w1(const float* __restrict__ W1) {
    int i = blockIdx.x * blockDim.x + threadIdx.x;
    if (i < (N_FEAT / 2) * HIDDEN) {
        int kk = i / HIDDEN;      // k-pair index
        int n  = i % HIDDEN;
        g_W1h[i] = packh(W1[(2 * kk) * HIDDEN + n], W1[(2 * kk + 1) * HIDDEN + n]);
    }
}

// ---------------- CSR build ----------------
__global__ void k_zero_cnt() {
    int i = blockIdx.x * blockDim.x + threadIdx.x;
    if (i < N_NODES) g_cnt[i] = 0;
    if (i == 0) g_rowptr[N_NODES] = N_EDGES;
}

__global__ void k_hist(const int* __restrict__ esrc) {
    int t = blockIdx.x * blockDim.x + threadIdx.x;
    if (t < N_EDGES / 4) {
        int4 s = ((const int4*)esrc)[t];
        atomicAdd(&g_cnt[s.x], 1);
        atomicAdd(&g_cnt[s.y], 1);
        atomicAdd(&g_cnt[s.z], 1);
        atomicAdd(&g_cnt[s.w], 1);
    }
}

// scan phase 1: per-1024-chunk sums
__global__ void k_scan1() {
    __shared__ int ws[32];
    int tid = threadIdx.x, lane = tid & 31, wid = tid >> 5;
    int i = blockIdx.x * 1024 + tid;
    int v = (i < N_NODES) ? g_cnt[i] : 0;
    #pragma unroll
    for (int d = 16; d >= 1; d >>= 1) v += __shfl_xor_sync(0xffffffffu, v, d);
    if (lane == 0) ws[wid] = v;
    __syncthreads();
    if (wid == 0) {
        int s = ws[lane];
        #pragma unroll
        for (int d = 16; d >= 1; d >>= 1) s += __shfl_xor_sync(0xffffffffu, s, d);
        if (lane == 0) g_chunksum[blockIdx.x] = s;
    }
}

// scan phase 3: chunk-prefix (folded) + in-chunk exclusive scan
__global__ void k_scan3() {
    __shared__ int ws[32];
    __shared__ int s_pre[4];
    int tid = threadIdx.x, lane = tid & 31, wid = tid >> 5;

    if (tid < 128) {
        int vp = (tid < blockIdx.x) ? g_chunksum[tid] : 0;
        #pragma unroll
        for (int d = 16; d >= 1; d >>= 1) vp += __shfl_xor_sync(0xffffffffu, vp, d);
        if (lane == 0) s_pre[wid] = vp;
    }

    int i = blockIdx.x * 1024 + tid;
    int v = (i < N_NODES) ? g_cnt[i] : 0;
    int x = v;
    #pragma unroll
    for (int d = 1; d < 32; d <<= 1) {
        int y = __shfl_up_sync(0xffffffffu, x, d);
        if (lane >= d) x += y;
    }
    if (lane == 31) ws[wid] = x;
    __syncthreads();
    if (wid == 0) {
        int w = ws[lane];
        int xs = w;
        #pragma unroll
        for (int d = 1; d < 32; d <<= 1) {
            int y = __shfl_up_sync(0xffffffffu, xs, d);
            if (lane >= d) xs += y;
        }
        ws[lane] = xs;
    }
    __syncthreads();
    int coff = s_pre[0] + s_pre[1] + s_pre[2] + s_pre[3];
    int warp_prefix = (wid > 0) ? ws[wid - 1] : 0;
    int excl = x - v + warp_prefix + coff;
    if (i < N_NODES) {
        g_rowptr[i] = excl;
        g_fill[i]   = excl;
        g_scale[i]  = (1.0f - ALPHA) / fmaxf((float)v, 1e-12f);
    }
}

__global__ void k_scatter(const int* __restrict__ esrc, const int* __restrict__ edst) {
    int t = blockIdx.x * blockDim.x + threadIdx.x;
    if (t < N_EDGES / 4) {
        int4 s = ((const int4*)esrc)[t];
        int4 d = ((const int4*)edst)[t];
        int p;
        p = atomicAdd(&g_fill[s.x], 1); g_csr[p] = d.x;
        p = atomicAdd(&g_fill[s.y], 1); g_csr[p] = d.y;
        p = atomicAdd(&g_fill[s.z], 1); g_csr[p] = d.z;
        p = atomicAdd(&g_fill[s.w], 1); g_csr[p] = d.w;
    }
}

// ---------------- fused GEMM: local = relu(x@W1) @ W2, fp16 MMA ----------------
// BM=128, BN=128, BK=32, 256 thr = 8 warps (4m x 2n), warp tile 32x64.
// A fp32 in smem -> half2 packed in regs; B pre-packed half2 in gmem.
#define GBM 128
#define GBK 32
#define ASTR 36
#define BSTR 136
#define A_BYTES (GBM * ASTR * 4)            // 18432
#define B_BYTES (16 * BSTR * 4)             // 8704 (16 k-pair rows)
#define STAGE_BYTES (A_BYTES + B_BYTES)     // 27136
#define HIDSTR 129
#define HID_BYTES (GBM * HIDSTR * 4)        // 66048
#define W2_OFF HID_BYTES                    // 66048
#define OUTS_OFF (W2_OFF + HIDDEN * N_CLASS * 4)  // 74240
#define OUTSTR 17
#define GEMM_SMEM (OUTS_OFF + GBM * OUTSTR * 4)   // 82944

__global__ __launch_bounds__(256, 2) void k_gemm(const float* __restrict__ x,
                                                 const float* __restrict__ W2) {
    extern __shared__ __align__(16) char sm[];
    float* W2s  = (float*)(sm + W2_OFF);
    float* outS = (float*)(sm + OUTS_OFF);
    float* hid  = (float*)sm;
    uint32_t smem_u32 = (uint32_t)__cvta_generic_to_shared(sm);

    int tid  = threadIdx.x;
    int lane = tid & 31;
    int warp = tid >> 5;
    int blockRow = blockIdx.x * GBM;

    int warpM = warp >> 1;   // 0..3
    int warpN = warp & 1;    // 0..1
    int grp = lane >> 2;     // 0..7
    int tig = lane & 3;      // 0..3

    for (int i = tid; i < HIDDEN * N_CLASS; i += 256) W2s[i] = W2[i];

    float acc[2][8][4];
    #pragma unroll
    for (int mt = 0; mt < 2; mt++)
        #pragma unroll
        for (int nt = 0; nt < 8; nt++)
            #pragma unroll
            for (int r = 0; r < 4; r++) acc[mt][nt][r] = 0.0f;

    auto load_tiles = [&](int kiter, int st) {
        int k0 = kiter * GBK;
        uint32_t abase = smem_u32 + st * STAGE_BYTES;
        uint32_t bbase = abase + A_BYTES;
        #pragma unroll
        for (int it = 0; it < 4; it++) {
            int idx = tid + it * 256;
            int r = idx >> 3, c4 = idx & 7;
            int gr = blockRow + r;
            if (gr >= N_NODES) gr = N_NODES - 1;
            cp16(abase + (r * ASTR + c4 * 4) * 4,
                 &x[(size_t)gr * N_FEAT + k0 + c4 * 4]);
        }
        // B: 16 k-pair rows x 128 uint32 (half2) per 32-k tile
        #pragma unroll
        for (int it = 0; it < 2; it++) {
            int idx = tid + it * 256;           // 0..511
            int r = idx >> 5, c4 = idx & 31;    // r: 0..15
            cp16(bbase + (r * BSTR + c4 * 4) * 4,
                 &g_W1h[(kiter * 16 + r) * HIDDEN + c4 * 4]);
        }
    };

    auto compute = [&](int st) {
        const uint32_t* As = (const uint32_t*)(sm + st * STAGE_BYTES);
        const uint32_t* Bs = (const uint32_t*)(sm + st * STAGE_BYTES + A_BYTES);
        #pragma unroll
        for (int ks = 0; ks < 2; ks++) {       // two k16 steps per 32-k tile
            int kb = ks * 16;
            uint32_t a[2][4];
            #pragma unroll
            for (int mt = 0; mt < 2; mt++) {
                int r0 = warpM * 32 + mt * 16 + grp;
                float2 lo0 = *(const float2*)&As[r0 * ASTR + kb + 2 * tig];
                float2 lo1 = *(const float2*)&As[(r0 + 8) * ASTR + kb + 2 * tig];
                float2 hi0 = *(const float2*)&As[r0 * ASTR + kb + 8 + 2 * tig];
                float2 hi1 = *(const float2*)&As[(r0 + 8) * ASTR + kb + 8 + 2 * tig];
                a[mt][0] = packh(lo0.x, lo0.y);
                a[mt][1] = packh(lo1.x, lo1.y);
                a[mt][2] = packh(hi0.x, hi0.y);
                a[mt][3] = packh(hi1.x, hi1.y);
            }
            #pragma unroll
            for (int nt = 0; nt < 8; nt++) {
                int col = warpN * 64 + nt * 8 + grp;
                uint32_t b0 = Bs[(ks * 8 + tig) * BSTR + col];
                uint32_t b1 = Bs[(ks * 8 + 4 + tig) * BSTR + col];
                mma_f16(acc[0][nt], a[0], b0, b1);
                mma_f16(acc[1][nt], a[1], b0, b1);
            }
        }
    };

    load_tiles(0, 0);
    CP_COMMIT;
    #pragma unroll 1
    for (int i = 0; i < N_FEAT / GBK; i++) {
        int st = i & 1;
        if (i + 1 < N_FEAT / GBK) {
            load_tiles(i + 1, st ^ 1);
            CP_COMMIT;
            CP_WAIT(1);
        } else {
            CP_WAIT(0);
        }
        __syncthreads();
        compute(st);
        __syncthreads();
    }

    // relu -> hid
    #pragma unroll
    for (int mt = 0; mt < 2; mt++) {
        int r0 = warpM * 32 + mt * 16 + grp;
        #pragma unroll
        for (int nt = 0; nt < 8; nt++) {
            int c = warpN * 64 + nt * 8 + tig * 2;
            hid[r0 * HIDSTR + c]           = fmaxf(acc[mt][nt][0], 0.f);
            hid[r0 * HIDSTR + c + 1]       = fmaxf(acc[mt][nt][1], 0.f);
            hid[(r0 + 8) * HIDSTR + c]     = fmaxf(acc[mt][nt][2], 0.f);
            hid[(r0 + 8) * HIDSTR + c + 1] = fmaxf(acc[mt][nt][3], 0.f);
        }
    }
    __syncthreads();

    // second gemm: out[128][16] = hid[128][128] @ W2[128][16], 2-way h split
    int r = tid & 127;
    int q = tid >> 7;  // 0..1
    float o[N_CLASS];
    #pragma unroll
    for (int c = 0; c < N_CLASS; c++) o[c] = 0.f;
    int h0 = q * 64;
    #pragma unroll 4
    for (int h = h0; h < h0 + 64; h++) {
        float v = hid[r * HIDSTR + h];
        #pragma unroll
        for (int c = 0; c < N_CLASS; c++) o[c] += v * W2s[h * N_CLASS + c];
    }
    if (q == 0) {
        #pragma unroll
        for (int c = 0; c < N_CLASS; c++) outS[r * OUTSTR + c] = o[c];
    }
    __syncthreads();
    if (q == 1) {
        int gr = blockRow + r;
        if (gr < N_NODES) {
            float vv[N_CLASS];
            #pragma unroll
            for (int c = 0; c < N_CLASS; c++) vv[c] = outS[r * OUTSTR + c] + o[c];
            #pragma unroll
            for (int j = 0; j < 4; j++) {
                float4 v4 = make_float4(vv[j*4+0], vv[j*4+1], vv[j*4+2], vv[j*4+3]);
                *(float4*)&g_local[gr * N_CLASS + j * 4] = v4;
            }
            uint4 h0v, h1v;
            h0v.x = packh(vv[0],  vv[1]);  h0v.y = packh(vv[2],  vv[3]);
            h0v.z = packh(vv[4],  vv[5]);  h0v.w = packh(vv[6],  vv[7]);
            h1v.x = packh(vv[8],  vv[9]);  h1v.y = packh(vv[10], vv[11]);
            h1v.z = packh(vv[12], vv[13]); h1v.w = packh(vv[14], vv[15]);
            *(uint4*)&g_localh[gr * N_CLASS]     = h0v;
            *(uint4*)&g_localh[gr * N_CLASS + 8] = h1v;
        }
    }
}

// ---------------- SpMM: 16 lanes = 16 classes per node, fp16 gather tables ----------------
template<int PHASE>
__global__ void k_spmm_t(float* __restrict__ outfinal) {
    const __half* tbl = (PHASE == 0) ? g_localh : g_tmph;
    int t = blockIdx.x * blockDim.x + threadIdx.x;
    int node = t >> 4;
    if (node >= N_NODES) return;
    int l16 = threadIdx.x & 15;
    unsigned mask = 0xFFFFu << (threadIdx.x & 16);

    int s = g_rowptr[node], e = g_rowptr[node + 1];
    float a = 0.f;
    int i = s;
    for (; i + 16 <= e; i += 16) {
        int idx = __ldg(&g_csr[i + l16]);
        #pragma unroll
        for (int q = 0; q < 16; q++) {
            int j = __shfl_sync(mask, idx, q, 16);
            a += __half2float(__ldg(&tbl[j * N_CLASS + l16]));
        }
    }
    int rem = e - i;
    if (rem) {
        int idx = (l16 < rem) ? __ldg(&g_csr[i + l16]) : 0;
        for (int q = 0; q < rem; q++) {
            int j = __shfl_sync(mask, idx, q, 16);
            a += __half2float(__ldg(&tbl[j * N_CLASS + l16]));
        }
    }
    float v = g_scale[node] * a + ALPHA * g_local[node * N_CLASS + l16];

    if (PHASE == 0) {
        g_tmph[node * N_CLASS + l16] = __float2half_rn(v);
    } else {
        float m = v;
        #pragma unroll
        for (int k = 8; k >= 1; k >>= 1) m = fmaxf(m, __shfl_xor_sync(mask, m, k, 16));
        float ex = __expf(v - m);
        float ss = ex;
        #pragma unroll
        for (int k = 8; k >= 1; k >>= 1) ss += __shfl_xor_sync(mask, ss, k, 16);
        outfinal[node * N_CLASS + l16] = v - m - __logf(ss);
    }
}

// ---------------- launch: fork CSR chain onto side stream, join before SpMM ----------------
// NOTE launch order: gemm is the 4th kernel launch so the profiler (-s window)
// captures it next round.
extern "C" void kernel_launch(void* const* d_in, const int* in_sizes, int n_in,
                              void* d_out, int out_size) {
    const float* x    = (const float*)d_in[0];
    const float* W1   = (const float*)d_in[1];
    const float* W2   = (const float*)d_in[2];
    const int*   esrc = (const int*)d_in[3];
    const int*   edst = (const int*)d_in[4];
    float* out = (float*)d_out;

    static cudaStream_t s2 = nullptr;
    static cudaEvent_t evFork = nullptr, evJoin = nullptr;
    if (s2 == nullptr) {
        cudaStreamCreateWithFlags(&s2, cudaStreamNonBlocking);
        cudaEventCreateWithFlags(&evFork, cudaEventDisableTiming);
        cudaEventCreateWithFlags(&evJoin, cudaEventDisableTiming);
        cudaFuncSetAttribute(k_gemm, cudaFuncAttributeMaxDynamicSharedMemorySize, GEMM_SMEM);
    }

    cudaEventRecord(evFork, 0);
    cudaStreamWaitEvent(s2, evFork, 0);

    // launches 1-2: CSR chain start (side stream)
    k_zero_cnt<<<(N_NODES + 255) / 256, 256, 0, s2>>>();
    k_hist<<<(N_EDGES / 4 + 255) / 256, 256, 0, s2>>>(esrc);

    // launches 3-4: feature chain (main stream) — gemm is launch #4
    k_cvt_w1<<<((N_FEAT / 2) * HIDDEN + 255) / 256, 256>>>(W1);
    k_gemm<<<(N_NODES + GBM - 1) / GBM, 256, GEMM_SMEM>>>(x, W2);

    // launches 5-7: CSR chain rest (side stream)
    k_scan1<<<NCHUNK, 1024, 0, s2>>>();
    k_scan3<<<NCHUNK, 1024, 0, s2>>>();
    k_scatter<<<(N_EDGES / 4 + 255) / 256, 256, 0, s2>>>(esrc, edst);
    cudaEventRecord(evJoin, s2);

    // join, then propagation
    cudaStreamWaitEvent(0, evJoin, 0);
    k_spmm_t<0><<<(N_NODES * N_CLASS + 255) / 256, 256>>>(nullptr);
    k_spmm_t<1><<<(N_NODES * N_CLASS + 255) / 256, 256>>>(out);
}

// round 11
// speedup vs baseline: 1.0984x; 1.0017x over previous
#include <cuda_runtime.h>
#include <cuda_bf16.h>
#include <cuda_fp16.h>
#include <cstdint>

#define N_NODES 100000
#define N_FEAT  512
#define HIDDEN  128
#define N_CLASS 16
#define N_EDGES 3200000
#define ALPHA   0.25f

#define NCHUNK 98   // ceil(100000/1024)

// ---------------- device scratch ----------------
__device__ float  g_local[N_NODES * N_CLASS];      // fp32 local logits (self term)
__device__ __half g_localh[N_NODES * N_CLASS];     // fp16 gather table, iter 1
__device__ __half g_tmph[N_NODES * N_CLASS];       // fp16 gather table, iter 2
__device__ int    g_cnt[N_NODES];
__device__ int    g_rowptr[N_NODES + 1];
__device__ int    g_fill[N_NODES];
__device__ float  g_scale[N_NODES];
__device__ int    g_csr[N_EDGES];
__device__ int    g_chunksum[NCHUNK];
__device__ uint32_t g_W1h[(N_FEAT / 2) * HIDDEN];  // W1 packed as half2 over k-pairs

// ---------------- helpers ----------------
__device__ __forceinline__ uint32_t packh(float a, float b) {
    __half2 t = __floats2half2_rn(a, b);
    return *(uint32_t*)&t;
}

__device__ __forceinline__ void mma_f16(float* d, const uint32_t* a,
                                        uint32_t b0, uint32_t b1) {
    asm volatile(
        "mma.sync.aligned.m16n8k16.row.col.f32.f16.f16.f32 "
        "{%0,%1,%2,%3},{%4,%5,%6,%7},{%8,%9},{%0,%1,%2,%3};\n"
        : "+f"(d[0]), "+f"(d[1]), "+f"(d[2]), "+f"(d[3])
        : "r"(a[0]), "r"(a[1]), "r"(a[2]), "r"(a[3]), "r"(b0), "r"(b1));
}

__device__ __forceinline__ void cp16(uint32_t dst, const void* src) {
    asm volatile("cp.async.cg.shared.global [%0], [%1], 16;\n"
                 :: "r"(dst), "l"(src) : "memory");
}
#define CP_COMMIT asm volatile("cp.async.commit_group;\n" ::: "memory")
#define CP_WAIT(N) asm volatile("cp.async.wait_group %0;\n" :: "n"(N) : "memory")

// ---------------- W1 pre-conversion: pack (k, k+1) pairs into half2 ----------------
__global__ void k_cvt_w1(const float* __restrict__ W1) {
    int i = blockIdx.x * blockDim.x + threadIdx.x;
    if (i < (N_FEAT / 2) * HIDDEN) {
        int kk = i / HIDDEN;      // k-pair index
        int n  = i % HIDDEN;
        g_W1h[i] = packh(W1[(2 * kk) * HIDDEN + n], W1[(2 * kk + 1) * HIDDEN + n]);
    }
}

// ---------------- CSR build ----------------
__global__ void k_zero_cnt() {
    int i = blockIdx.x * blockDim.x + threadIdx.x;
    if (i < N_NODES) g_cnt[i] = 0;
    if (i == 0) g_rowptr[N_NODES] = N_EDGES;
}

__global__ void k_hist(const int* __restrict__ esrc) {
    int t = blockIdx.x * blockDim.x + threadIdx.x;
    if (t < N_EDGES / 4) {
        int4 s = ((const int4*)esrc)[t];
        atomicAdd(&g_cnt[s.x], 1);
        atomicAdd(&g_cnt[s.y], 1);
        atomicAdd(&g_cnt[s.z], 1);
        atomicAdd(&g_cnt[s.w], 1);
    }
}

// scan phase 1: per-1024-chunk sums
__global__ void k_scan1() {
    __shared__ int ws[32];
    int tid = threadIdx.x, lane = tid & 31, wid = tid >> 5;
    int i = blockIdx.x * 1024 + tid;
    int v = (i < N_NODES) ? g_cnt[i] : 0;
    #pragma unroll
    for (int d = 16; d >= 1; d >>= 1) v += __shfl_xor_sync(0xffffffffu, v, d);
    if (lane == 0) ws[wid] = v;
    __syncthreads();
    if (wid == 0) {
        int s = ws[lane];
        #pragma unroll
        for (int d = 16; d >= 1; d >>= 1) s += __shfl_xor_sync(0xffffffffu, s, d);
        if (lane == 0) g_chunksum[blockIdx.x] = s;
    }
}

// scan phase 3: chunk-prefix (folded) + in-chunk exclusive scan
__global__ void k_scan3() {
    __shared__ int ws[32];
    __shared__ int s_pre[4];
    int tid = threadIdx.x, lane = tid & 31, wid = tid >> 5;

    if (tid < 128) {
        int vp = (tid < blockIdx.x) ? g_chunksum[tid] : 0;
        #pragma unroll
        for (int d = 16; d >= 1; d >>= 1) vp += __shfl_xor_sync(0xffffffffu, vp, d);
        if (lane == 0) s_pre[wid] = vp;
    }

    int i = blockIdx.x * 1024 + tid;
    int v = (i < N_NODES) ? g_cnt[i] : 0;
    int x = v;
    #pragma unroll
    for (int d = 1; d < 32; d <<= 1) {
        int y = __shfl_up_sync(0xffffffffu, x, d);
        if (lane >= d) x += y;
    }
    if (lane == 31) ws[wid] = x;
    __syncthreads();
    if (wid == 0) {
        int w = ws[lane];
        int xs = w;
        #pragma unroll
        for (int d = 1; d < 32; d <<= 1) {
            int y = __shfl_up_sync(0xffffffffu, xs, d);
            if (lane >= d) xs += y;
        }
        ws[lane] = xs;
    }
    __syncthreads();
    int coff = s_pre[0] + s_pre[1] + s_pre[2] + s_pre[3];
    int warp_prefix = (wid > 0) ? ws[wid - 1] : 0;
    int excl = x - v + warp_prefix + coff;
    if (i < N_NODES) {
        g_rowptr[i] = excl;
        g_fill[i]   = excl;
        g_scale[i]  = (1.0f - ALPHA) / fmaxf((float)v, 1e-12f);
    }
}

__global__ void k_scatter(const int* __restrict__ esrc, const int* __restrict__ edst) {
    int t = blockIdx.x * blockDim.x + threadIdx.x;
    if (t < N_EDGES / 4) {
        int4 s = ((const int4*)esrc)[t];
        int4 d = ((const int4*)edst)[t];
        int p;
        p = atomicAdd(&g_fill[s.x], 1); g_csr[p] = d.x;
        p = atomicAdd(&g_fill[s.y], 1); g_csr[p] = d.y;
        p = atomicAdd(&g_fill[s.z], 1); g_csr[p] = d.z;
        p = atomicAdd(&g_fill[s.w], 1); g_csr[p] = d.w;
    }
}

// ---------------- fused GEMM: local = relu(x@W1) @ W2, fp16 MMA ----------------
// BM=128, BN=128, BK=32, 256 thr = 8 warps (4m x 2n), warp tile 32x64.
// 3-stage cp.async pipeline, single __syncthreads per k-tile (loads issued
// AFTER the barrier -> stage-reuse race-free with one sync).
#define GBM 128
#define GBK 32
#define ASTR 36
#define BSTR 136
#define NSTAGE 3
#define A_BYTES (GBM * ASTR * 4)            // 18432
#define B_BYTES (16 * BSTR * 4)             // 8704 (16 k-pair rows)
#define STAGE_BYTES (A_BYTES + B_BYTES)     // 27136
#define STAGES_BYTES (NSTAGE * STAGE_BYTES) // 81408
#define HIDSTR 129
#define HID_BYTES (GBM * HIDSTR * 4)        // 66048 (overlays stages)
#define W2_OFF STAGES_BYTES                 // 81408
#define OUTS_OFF (W2_OFF + HIDDEN * N_CLASS * 4)  // 89600
#define OUTSTR 17
#define GEMM_SMEM (OUTS_OFF + GBM * OUTSTR * 4)   // 98304
#define NKITER (N_FEAT / GBK)               // 16

__global__ __launch_bounds__(256, 2) void k_gemm(const float* __restrict__ x,
                                                 const float* __restrict__ W2) {
    extern __shared__ __align__(16) char sm[];
    float* W2s  = (float*)(sm + W2_OFF);
    float* outS = (float*)(sm + OUTS_OFF);
    float* hid  = (float*)sm;
    uint32_t smem_u32 = (uint32_t)__cvta_generic_to_shared(sm);

    int tid  = threadIdx.x;
    int lane = tid & 31;
    int warp = tid >> 5;
    int blockRow = blockIdx.x * GBM;

    int warpM = warp >> 1;   // 0..3
    int warpN = warp & 1;    // 0..1
    int grp = lane >> 2;     // 0..7
    int tig = lane & 3;      // 0..3

    for (int i = tid; i < HIDDEN * N_CLASS; i += 256) W2s[i] = W2[i];

    float acc[2][8][4];
    #pragma unroll
    for (int mt = 0; mt < 2; mt++)
        #pragma unroll
        for (int nt = 0; nt < 8; nt++)
            #pragma unroll
            for (int r = 0; r < 4; r++) acc[mt][nt][r] = 0.0f;

    auto load_tiles = [&](int kiter) {
        int st = kiter % NSTAGE;
        int k0 = kiter * GBK;
        uint32_t abase = smem_u32 + st * STAGE_BYTES;
        uint32_t bbase = abase + A_BYTES;
        #pragma unroll
        for (int it = 0; it < 4; it++) {
            int idx = tid + it * 256;
            int r = idx >> 3, c4 = idx & 7;
            int gr = blockRow + r;
            if (gr >= N_NODES) gr = N_NODES - 1;
            cp16(abase + (r * ASTR + c4 * 4) * 4,
                 &x[(size_t)gr * N_FEAT + k0 + c4 * 4]);
        }
        #pragma unroll
        for (int it = 0; it < 2; it++) {
            int idx = tid + it * 256;           // 0..511
            int r = idx >> 5, c4 = idx & 31;    // r: 0..15
            cp16(bbase + (r * BSTR + c4 * 4) * 4,
                 &g_W1h[(kiter * 16 + r) * HIDDEN + c4 * 4]);
        }
        CP_COMMIT;
    };

    auto compute = [&](int kiter) {
        int st = kiter % NSTAGE;
        const uint32_t* As = (const uint32_t*)(sm + st * STAGE_BYTES);
        const uint32_t* Bs = (const uint32_t*)(sm + st * STAGE_BYTES + A_BYTES);
        #pragma unroll
        for (int ks = 0; ks < 2; ks++) {       // two k16 steps per 32-k tile
            int kb = ks * 16;
            uint32_t a[2][4];
            #pragma unroll
            for (int mt = 0; mt < 2; mt++) {
                int r0 = warpM * 32 + mt * 16 + grp;
                float2 lo0 = *(const float2*)&As[r0 * ASTR + kb + 2 * tig];
                float2 lo1 = *(const float2*)&As[(r0 + 8) * ASTR + kb + 2 * tig];
                float2 hi0 = *(const float2*)&As[r0 * ASTR + kb + 8 + 2 * tig];
                float2 hi1 = *(const float2*)&As[(r0 + 8) * ASTR + kb + 8 + 2 * tig];
                a[mt][0] = packh(lo0.x, lo0.y);
                a[mt][1] = packh(lo1.x, lo1.y);
                a[mt][2] = packh(hi0.x, hi0.y);
                a[mt][3] = packh(hi1.x, hi1.y);
            }
            #pragma unroll
            for (int nt = 0; nt < 8; nt++) {
                int col = warpN * 64 + nt * 8 + grp;
                uint32_t b0 = Bs[(ks * 8 + tig) * BSTR + col];
                uint32_t b1 = Bs[(ks * 8 + 4 + tig) * BSTR + col];
                mma_f16(acc[0][nt], a[0], b0, b1);
                mma_f16(acc[1][nt], a[1], b0, b1);
            }
        }
    };

    // 3-stage pipeline: prologue fills stages 0,1
    load_tiles(0);
    load_tiles(1);
    #pragma unroll 1
    for (int i = 0; i < NKITER; i++) {
        if (i < NKITER - 2) { CP_WAIT(1); } else { CP_WAIT(0); }
        __syncthreads();                    // single barrier per tile
        if (i + 2 < NKITER) load_tiles(i + 2);  // issued after barrier: race-free
        compute(i);
    }
    __syncthreads();                        // all compute done before hid overlay

    // relu -> hid
    #pragma unroll
    for (int mt = 0; mt < 2; mt++) {
        int r0 = warpM * 32 + mt * 16 + grp;
        #pragma unroll
        for (int nt = 0; nt < 8; nt++) {
            int c = warpN * 64 + nt * 8 + tig * 2;
            hid[r0 * HIDSTR + c]           = fmaxf(acc[mt][nt][0], 0.f);
            hid[r0 * HIDSTR + c + 1]       = fmaxf(acc[mt][nt][1], 0.f);
            hid[(r0 + 8) * HIDSTR + c]     = fmaxf(acc[mt][nt][2], 0.f);
            hid[(r0 + 8) * HIDSTR + c + 1] = fmaxf(acc[mt][nt][3], 0.f);
        }
    }
    __syncthreads();

    // second gemm: out[128][16] = hid[128][128] @ W2[128][16], 2-way h split
    int r = tid & 127;
    int q = tid >> 7;  // 0..1
    float o[N_CLASS];
    #pragma unroll
    for (int c = 0; c < N_CLASS; c++) o[c] = 0.f;
    int h0 = q * 64;
    #pragma unroll 4
    for (int h = h0; h < h0 + 64; h++) {
        float v = hid[r * HIDSTR + h];
        #pragma unroll
        for (int c = 0; c < N_CLASS; c++) o[c] += v * W2s[h * N_CLASS + c];
    }
    if (q == 0) {
        #pragma unroll
        for (int c = 0; c < N_CLASS; c++) outS[r * OUTSTR + c] = o[c];
    }
    __syncthreads();
    if (q == 1) {
        int gr = blockRow + r;
        if (gr < N_NODES) {
            float vv[N_CLASS];
            #pragma unroll
            for (int c = 0; c < N_CLASS; c++) vv[c] = outS[r * OUTSTR + c] + o[c];
            #pragma unroll
            for (int j = 0; j < 4; j++) {
                float4 v4 = make_float4(vv[j*4+0], vv[j*4+1], vv[j*4+2], vv[j*4+3]);
                *(float4*)&g_local[gr * N_CLASS + j * 4] = v4;
            }
            uint4 h0v, h1v;
            h0v.x = packh(vv[0],  vv[1]);  h0v.y = packh(vv[2],  vv[3]);
            h0v.z = packh(vv[4],  vv[5]);  h0v.w = packh(vv[6],  vv[7]);
            h1v.x = packh(vv[8],  vv[9]);  h1v.y = packh(vv[10], vv[11]);
            h1v.z = packh(vv[12], vv[13]); h1v.w = packh(vv[14], vv[15]);
            *(uint4*)&g_localh[gr * N_CLASS]     = h0v;
            *(uint4*)&g_localh[gr * N_CLASS + 8] = h1v;
        }
    }
}

// ---------------- SpMM: 16 lanes = 16 classes per node, fp16 gather tables ----------------
template<int PHASE>
__global__ void k_spmm_t(float* __restrict__ outfinal) {
    const __half* tbl = (PHASE == 0) ? g_localh : g_tmph;
    int t = blockIdx.x * blockDim.x + threadIdx.x;
    int node = t >> 4;
    if (node >= N_NODES) return;
    int l16 = threadIdx.x & 15;
    unsigned mask = 0xFFFFu << (threadIdx.x & 16);

    int s = g_rowptr[node], e = g_rowptr[node + 1];
    float a = 0.f;
    int i = s;
    for (; i + 16 <= e; i += 16) {
        int idx = __ldg(&g_csr[i + l16]);
        #pragma unroll
        for (int q = 0; q < 16; q++) {
            int j = __shfl_sync(mask, idx, q, 16);
            a += __half2float(__ldg(&tbl[j * N_CLASS + l16]));
        }
    }
    int rem = e - i;
    if (rem) {
        int idx = (l16 < rem) ? __ldg(&g_csr[i + l16]) : 0;
        for (int q = 0; q < rem; q++) {
            int j = __shfl_sync(mask, idx, q, 16);
            a += __half2float(__ldg(&tbl[j * N_CLASS + l16]));
        }
    }
    float v = g_scale[node] * a + ALPHA * g_local[node * N_CLASS + l16];

    if (PHASE == 0) {
        g_tmph[node * N_CLASS + l16] = __float2half_rn(v);
    } else {
        float m = v;
        #pragma unroll
        for (int k = 8; k >= 1; k >>= 1) m = fmaxf(m, __shfl_xor_sync(mask, m, k, 16));
        float ex = __expf(v - m);
        float ss = ex;
        #pragma unroll
        for (int k = 8; k >= 1; k >>= 1) ss += __shfl_xor_sync(mask, ss, k, 16);
        outfinal[node * N_CLASS + l16] = v - m - __logf(ss);
    }
}

// ---------------- launch: fork CSR chain onto side stream, join before SpMM ----------------
// k_gemm stays launch #4 (the profiler's capture slot) to verify this round's change.
extern "C" void kernel_launch(void* const* d_in, const int* in_sizes, int n_in,
                              void* d_out, int out_size) {
    const float* x    = (const float*)d_in[0];
    const float* W1   = (const float*)d_in[1];
    const float* W2   = (const float*)d_in[2];
    const int*   esrc = (const int*)d_in[3];
    const int*   edst = (const int*)d_in[4];
    float* out = (float*)d_out;

    static cudaStream_t s2 = nullptr;
    static cudaEvent_t evFork = nullptr, evJoin = nullptr;
    if (s2 == nullptr) {
        cudaStreamCreateWithFlags(&s2, cudaStreamNonBlocking);
        cudaEventCreateWithFlags(&evFork, cudaEventDisableTiming);
        cudaEventCreateWithFlags(&evJoin, cudaEventDisableTiming);
        cudaFuncSetAttribute(k_gemm, cudaFuncAttributeMaxDynamicSharedMemorySize, GEMM_SMEM);
    }

    cudaEventRecord(evFork, 0);
    cudaStreamWaitEvent(s2, evFork, 0);

    // launches 1-2: CSR chain start (side stream)
    k_zero_cnt<<<(N_NODES + 255) / 256, 256, 0, s2>>>();
    k_hist<<<(N_EDGES / 4 + 255) / 256, 256, 0, s2>>>(esrc);

    // launches 3-4: feature chain (main stream) — gemm is launch #4
    k_cvt_w1<<<((N_FEAT / 2) * HIDDEN + 255) / 256, 256>>>(W1);
    k_gemm<<<(N_NODES + GBM - 1) / GBM, 256, GEMM_SMEM>>>(x, W2);

    // launches 5-7: CSR chain rest (side stream)
    k_scan1<<<NCHUNK, 1024, 0, s2>>>();
    k_scan3<<<NCHUNK, 1024, 0, s2>>>();
    k_scatter<<<(N_EDGES / 4 + 255) / 256, 256, 0, s2>>>(esrc, edst);
    cudaEventRecord(evJoin, s2);

    // join, then propagation
    cudaStreamWaitEvent(0, evJoin, 0);
    k_spmm_t<0><<<(N_NODES * N_CLASS + 255) / 256, 256>>>(nullptr);
    k_spmm_t<1><<<(N_NODES * N_CLASS + 255) / 256, 256>>>(out);
}